// round 5
// baseline (speedup 1.0000x reference)
#include <cuda_runtime.h>
#include <cuda_bf16.h>
#include <mma.h>
#include <cstdint>

using namespace nvcuda;

#define Lc   8
#define Hc   4
#define Qc   64
#define Dc   512
#define Nc   2048
#define DFFc 2048

// ---------------- device scratch (no allocations allowed) ----------------
__device__ float g_X[Dc * Nc];
__device__ float g_attn[Dc * Nc];
__device__ float g_KX[Hc * Qc * Nc];
__device__ float g_Y[Hc * Dc * Nc];
__device__ float g_ff1[DFFc * Nc];

// Split a float4 into bf16 high/low parts and store 4+4 bf16.
__device__ __forceinline__ void split_store4(__nv_bfloat16* __restrict__ Hd,
                                             __nv_bfloat16* __restrict__ Ld,
                                             float4 v)
{
    __nv_bfloat162 h0 = __floats2bfloat162_rn(v.x, v.y);
    __nv_bfloat162 h1 = __floats2bfloat162_rn(v.z, v.w);
    float2 f0 = __bfloat1622float2(h0);
    float2 f1 = __bfloat1622float2(h1);
    __nv_bfloat162 l0 = __floats2bfloat162_rn(v.x - f0.x, v.y - f0.y);
    __nv_bfloat162 l1 = __floats2bfloat162_rn(v.z - f1.x, v.w - f1.y);
    *(__nv_bfloat162*)(Hd)     = h0;
    *(__nv_bfloat162*)(Hd + 2) = h1;
    *(__nv_bfloat162*)(Ld)     = l0;
    *(__nv_bfloat162*)(Ld + 2) = l1;
}

// monotonic float<->uint encoding for atomicMax on fp32
__device__ __forceinline__ unsigned enc_f(float f) {
    unsigned u = __float_as_uint(f);
    return (u & 0x80000000u) ? ~u : (u | 0x80000000u);
}
__device__ __forceinline__ float dec_f(unsigned v) {
    return __uint_as_float((v & 0x80000000u) ? (v ^ 0x80000000u) : ~v);
}

// ============ WMMA bf16 3x GEMM: C = A@B (+bias)(+relu)(+residual) ========
// A:[M,K] row-major, B:[K,N] row-major, C:[M,N] row-major.
// Block tile BM x BN x 32, double-buffered smem, warp tile (MF*16)x(NF*16).
// mode 0: C=AB (direct store); 1: C=relu(AB+bias); 2: C=AB+bias+R
template<int BM, int BN, int WARPS_M, int WARPS_N>
__global__ void __launch_bounds__(WARPS_M * WARPS_N * 32) wmma_gemm(
    const float* __restrict__ A, const float* __restrict__ B,
    float* __restrict__ C, int M, int N, int K,
    long long strideA, long long strideC,
    const float* __restrict__ bias, const float* __restrict__ R, int mode)
{
    constexpr int THREADS = WARPS_M * WARPS_N * 32;
    constexpr int BK = 32;
    constexpr int AP = 48;
    constexpr int BP = BN + 16;
    constexpr int A_ELE = BM * AP;
    constexpr int B_ELE = BK * BP;
    constexpr int BUFE  = 2 * A_ELE + 2 * B_ELE;
    constexpr int MF = BM / (WARPS_M * 16);
    constexpr int NF = BN / (WARPS_N * 16);
    constexpr int AF4T = BM * (BK / 4) / THREADS;
    constexpr int BF4T = BK * (BN / 4) / THREADS;

    extern __shared__ char smc[];
    __nv_bfloat16* smb = (__nv_bfloat16*)smc;

    A += (size_t)blockIdx.z * strideA;
    C += (size_t)blockIdx.z * strideC;
    const int tid = threadIdx.x;
    const int w   = tid >> 5;
    const int bm  = blockIdx.y * BM;
    const int bn  = blockIdx.x * BN;
    const int wm0 = (w % WARPS_M) * (MF * 16);
    const int wn0 = (w / WARPS_M) * (NF * 16);

    float4 a_reg[AF4T], b_reg[BF4T];

#define GLOAD(k0)                                                              \
    {                                                                          \
        _Pragma("unroll")                                                      \
        for (int p = 0; p < AF4T; p++) {                                       \
            const int id = tid + p * THREADS;                                  \
            const int r = id >> 3, c4 = id & 7;                                \
            a_reg[p] = *(const float4*)&A[(size_t)(bm + r) * K + (k0) + c4*4]; \
        }                                                                      \
        _Pragma("unroll")                                                      \
        for (int p = 0; p < BF4T; p++) {                                       \
            const int id = tid + p * THREADS;                                  \
            const int r = id / (BN / 4), c4 = id % (BN / 4);                   \
            b_reg[p] = *(const float4*)&B[(size_t)((k0) + r) * N + bn + c4*4]; \
        }                                                                      \
    }

#define SSTORE(buf)                                                            \
    {                                                                          \
        __nv_bfloat16* aH = smb + (buf) * BUFE;                                \
        __nv_bfloat16* aL = aH + A_ELE;                                        \
        __nv_bfloat16* bH = aH + 2 * A_ELE;                                    \
        __nv_bfloat16* bL = bH + B_ELE;                                        \
        _Pragma("unroll")                                                      \
        for (int p = 0; p < AF4T; p++) {                                       \
            const int id = tid + p * THREADS;                                  \
            const int r = id >> 3, c4 = id & 7;                                \
            split_store4(aH + r * AP + c4 * 4, aL + r * AP + c4 * 4, a_reg[p]);\
        }                                                                      \
        _Pragma("unroll")                                                      \
        for (int p = 0; p < BF4T; p++) {                                       \
            const int id = tid + p * THREADS;                                  \
            const int r = id / (BN / 4), c4 = id % (BN / 4);                   \
            split_store4(bH + r * BP + c4 * 4, bL + r * BP + c4 * 4, b_reg[p]);\
        }                                                                      \
    }

    wmma::fragment<wmma::accumulator, 16, 16, 16, float> acc[MF][NF];
#pragma unroll
    for (int i = 0; i < MF; i++)
#pragma unroll
        for (int j = 0; j < NF; j++) wmma::fill_fragment(acc[i][j], 0.f);

    GLOAD(0);
    SSTORE(0);
    __syncthreads();

    const int KT = K / BK;
    for (int kt = 0; kt < KT; kt++) {
        const int cur = kt & 1;
        if (kt + 1 < KT) GLOAD((kt + 1) * BK);

        const __nv_bfloat16* aH = smb + cur * BUFE;
        const __nv_bfloat16* aL = aH + A_ELE;
        const __nv_bfloat16* bH = aH + 2 * A_ELE;
        const __nv_bfloat16* bL = bH + B_ELE;

#pragma unroll
        for (int kks = 0; kks < 2; kks++) {
            const int kk = kks * 16;
            wmma::fragment<wmma::matrix_a, 16, 16, 16, __nv_bfloat16, wmma::row_major> fAh[MF], fAl[MF];
            wmma::fragment<wmma::matrix_b, 16, 16, 16, __nv_bfloat16, wmma::row_major> fBh[NF], fBl[NF];
#pragma unroll
            for (int i = 0; i < MF; i++) {
                wmma::load_matrix_sync(fAh[i], aH + (wm0 + i * 16) * AP + kk, AP);
                wmma::load_matrix_sync(fAl[i], aL + (wm0 + i * 16) * AP + kk, AP);
            }
#pragma unroll
            for (int j = 0; j < NF; j++) {
                wmma::load_matrix_sync(fBh[j], bH + kk * BP + wn0 + j * 16, BP);
                wmma::load_matrix_sync(fBl[j], bL + kk * BP + wn0 + j * 16, BP);
            }
#pragma unroll
            for (int i = 0; i < MF; i++)
#pragma unroll
                for (int j = 0; j < NF; j++) {
                    wmma::mma_sync(acc[i][j], fAh[i], fBh[j], acc[i][j]);
                    wmma::mma_sync(acc[i][j], fAh[i], fBl[j], acc[i][j]);
                    wmma::mma_sync(acc[i][j], fAl[i], fBh[j], acc[i][j]);
                }
        }

        if (kt + 1 < KT) {
            SSTORE(cur ^ 1);
            __syncthreads();
        }
    }

    if (mode == 0) {
#pragma unroll
        for (int i = 0; i < MF; i++)
#pragma unroll
            for (int j = 0; j < NF; j++)
                wmma::store_matrix_sync(
                    &C[(size_t)(bm + wm0 + i * 16) * N + bn + wn0 + j * 16],
                    acc[i][j], N, wmma::mem_row_major);
    } else {
        __syncthreads();
        float* cs = (float*)smc;
#pragma unroll
        for (int i = 0; i < MF; i++)
#pragma unroll
            for (int j = 0; j < NF; j++)
                wmma::store_matrix_sync(
                    cs + (size_t)(wm0 + i * 16) * BN + wn0 + j * 16,
                    acc[i][j], BN, wmma::mem_row_major);
        __syncthreads();

        constexpr int CF4T = BM * BN / 4 / THREADS;
#pragma unroll
        for (int p = 0; p < CF4T; p++) {
            const int id = tid + p * THREADS;
            const int row = id / (BN / 4), c4 = id % (BN / 4);
            float4 v = ((const float4*)cs)[id];
            const int grow = bm + row;
            const float bv = bias[grow];
            v.x += bv; v.y += bv; v.z += bv; v.w += bv;
            if (mode == 1) {
                v.x = fmaxf(v.x, 0.f); v.y = fmaxf(v.y, 0.f);
                v.z = fmaxf(v.z, 0.f); v.w = fmaxf(v.w, 0.f);
            } else {
                float4 r4 = *(const float4*)&R[(size_t)grow * N + bn + c4 * 4];
                v.x += r4.x; v.y += r4.y; v.z += r4.z; v.w += r4.w;
            }
            *(float4*)&C[(size_t)grow * N + bn + c4 * 4] = v;
        }
    }
#undef GLOAD
#undef SSTORE
}

// ====== fused gram + argmax + scatter =====================================
// One block = 64-row stripe of head h. Computes S-row tiles on the fly via
// WMMA, keeps running row max + candidate list, then scatters
// attn[:,m] += w_n * Y[h][:,n] for every final hit m of every row n.
#define CAND 96
__global__ void __launch_bounds__(256) gram_argmax_scatter(
    const float* __restrict__ KX, const float* __restrict__ Y,
    float* __restrict__ attn)
{
    constexpr int AP = 72;    // A pitch (64 + 8)
    constexpr int BPp = 136;  // B pitch (128 + 8)
    constexpr int CP = 132;   // C pitch (128 + 4)

    extern __shared__ char smc[];
    __nv_bfloat16* aH = (__nv_bfloat16*)(smc);
    __nv_bfloat16* aL = (__nv_bfloat16*)(smc + 9216);
    __nv_bfloat16* bH = (__nv_bfloat16*)(smc + 18432);
    __nv_bfloat16* bL = (__nv_bfloat16*)(smc + 35840);
    float*    Cs   = (float*)(smc + 53248);
    unsigned* rm   = (unsigned*)(smc + 87040);
    int*      cnt  = (int*)(smc + 87296);
    float*    wrow = (float*)(smc + 87552);
    int*      cm   = (int*)(smc + 87808);
    float*    csv  = (float*)(smc + 112384);
    float*    wy   = (float*)(smc + 136960);

    const int h  = blockIdx.y;
    const int r0 = blockIdx.x * 64;
    const float* A = KX + (size_t)h * Qc * Nc;

    const int tid = threadIdx.x;
    const int w   = tid >> 5;
    const int wm0 = (w & 1) * 32;
    const int wn0 = (w >> 1) * 32;

    if (tid < 64) { rm[tid] = enc_f(-1e30f); cnt[tid] = 0; }

    // A stripe: KX[q][r0..r0+63], q=0..63 -> col_major operand
#pragma unroll
    for (int p = 0; p < 4; p++) {
        const int id = tid + p * 256;
        const int q = id >> 4, c4 = id & 15;
        float4 v = *(const float4*)&A[(size_t)q * Nc + r0 + c4 * 4];
        split_store4(aH + q * AP + c4 * 4, aL + q * AP + c4 * 4, v);
    }
    __syncthreads();

    for (int mt = 0; mt < Nc / 128; mt++) {
        const int m0 = mt * 128;
        // B tile: KX[q][m0..m0+127]
#pragma unroll
        for (int p = 0; p < 8; p++) {
            const int id = tid + p * 256;
            const int q = id >> 5, c4 = id & 31;
            float4 v = *(const float4*)&A[(size_t)q * Nc + m0 + c4 * 4];
            split_store4(bH + q * BPp + c4 * 4, bL + q * BPp + c4 * 4, v);
        }
        __syncthreads();

        wmma::fragment<wmma::accumulator, 16, 16, 16, float> acc[2][2];
#pragma unroll
        for (int i = 0; i < 2; i++)
#pragma unroll
            for (int j = 0; j < 2; j++) wmma::fill_fragment(acc[i][j], 0.f);

#pragma unroll
        for (int kks = 0; kks < 4; kks++) {
            const int kk = kks * 16;
            wmma::fragment<wmma::matrix_a, 16, 16, 16, __nv_bfloat16, wmma::col_major> fAh[2], fAl[2];
            wmma::fragment<wmma::matrix_b, 16, 16, 16, __nv_bfloat16, wmma::row_major> fBh[2], fBl[2];
#pragma unroll
            for (int i = 0; i < 2; i++) {
                wmma::load_matrix_sync(fAh[i], aH + kk * AP + wm0 + i * 16, AP);
                wmma::load_matrix_sync(fAl[i], aL + kk * AP + wm0 + i * 16, AP);
            }
#pragma unroll
            for (int j = 0; j < 2; j++) {
                wmma::load_matrix_sync(fBh[j], bH + kk * BPp + wn0 + j * 16, BPp);
                wmma::load_matrix_sync(fBl[j], bL + kk * BPp + wn0 + j * 16, BPp);
            }
#pragma unroll
            for (int i = 0; i < 2; i++)
#pragma unroll
                for (int j = 0; j < 2; j++) {
                    wmma::mma_sync(acc[i][j], fAh[i], fBh[j], acc[i][j]);
                    wmma::mma_sync(acc[i][j], fAh[i], fBl[j], acc[i][j]);
                    wmma::mma_sync(acc[i][j], fAl[i], fBh[j], acc[i][j]);
                }
        }
#pragma unroll
        for (int i = 0; i < 2; i++)
#pragma unroll
            for (int j = 0; j < 2; j++)
                wmma::store_matrix_sync(Cs + (wm0 + i * 16) * CP + wn0 + j * 16,
                                        acc[i][j], CP, wmma::mem_row_major);
        __syncthreads();

        // per-row tile max -> merge into running max
        const int r = tid >> 2;
        const int c0 = (tid & 3) * 32;
        float tm = -1e30f;
#pragma unroll
        for (int c = 0; c < 32; c++) tm = fmaxf(tm, Cs[r * CP + c0 + c]);
        tm = fmaxf(tm, __shfl_xor_sync(0xffffffffu, tm, 1, 4));
        tm = fmaxf(tm, __shfl_xor_sync(0xffffffffu, tm, 2, 4));
        if ((tid & 3) == 0) atomicMax(&rm[r], enc_f(tm));
        __syncthreads();

        // candidate insertion against updated running max
        const float thr = dec_f(rm[r]) - 0.5f;
#pragma unroll
        for (int c = 0; c < 32; c++) {
            const float v = Cs[r * CP + c0 + c];
            if (v >= thr) {
                int pos = atomicAdd(&cnt[r], 1);
                if (pos < CAND) {
                    cm[r * CAND + pos] = m0 + c0 + c;
                    csv[r * CAND + pos] = v;
                }
            }
        }
        __syncthreads();
    }

    // finalize: filter candidates by final max, compact, compute weight
    if (tid < 64) {
        const float fmax = dec_f(rm[tid]);
        const float thrF = fmax - 0.5f;
        const int nc = cnt[tid] < CAND ? cnt[tid] : CAND;
        int hits = 0;
        for (int j = 0; j < nc; j++) {
            if (csv[tid * CAND + j] >= thrF) {
                cm[tid * CAND + hits] = cm[tid * CAND + j];
                hits++;
            }
        }
        cnt[tid] = hits;
        wrow[tid] = (fabsf(fmax) > 0.5f && hits > 0) ? 1.f / (float)hits : 0.f;
    }
    __syncthreads();

    // scatter
    const float* Yh = Y + (size_t)h * Dc * Nc;
    for (int r = 0; r < 64; r++) {
        const float wv = wrow[r];
        const int hits = cnt[r];
        if (wv == 0.f || hits == 0) continue;
        const int n = r0 + r;
#pragma unroll
        for (int p = 0; p < 2; p++) {
            const int d = tid + p * 256;
            wy[d] = wv * Yh[(size_t)d * Nc + n];
        }
        __syncthreads();
        for (int j = 0; j < hits; j++) {
            const int m = cm[r * CAND + j];
#pragma unroll
            for (int p = 0; p < 2; p++) {
                const int d = tid + p * 256;
                atomicAdd(&attn[(size_t)d * Nc + m], wy[d]);
            }
        }
        __syncthreads();
    }
}

// --------------------------------------------------------------------------
extern "C" void kernel_launch(void* const* d_in, const int* in_sizes, int n_in,
                              void* d_out, int out_size)
{
    const float* X  = (const float*)d_in[0];
    const float* Kp = (const float*)d_in[1];
    const float* Vp = (const float*)d_in[2];
    const float* W1 = (const float*)d_in[3];
    const float* b1 = (const float*)d_in[4];
    const float* W2 = (const float*)d_in[5];
    const float* b2 = (const float*)d_in[6];

    float *gX, *gAttn, *gKX, *gY, *gFF1;
    cudaGetSymbolAddress((void**)&gX,    g_X);
    cudaGetSymbolAddress((void**)&gAttn, g_attn);
    cudaGetSymbolAddress((void**)&gKX,   g_KX);
    cudaGetSymbolAddress((void**)&gY,    g_Y);
    cudaGetSymbolAddress((void**)&gFF1,  g_ff1);

    const int SM128 = 2 * (2 * 128 * 48 * 2 + 2 * 32 * 144 * 2);  // 86016
    const int SM64  = 2 * (2 *  64 * 48 * 2 + 2 * 32 * 144 * 2);  // 61440
    const int SMKX  = 2 * (2 *  64 * 48 * 2 + 2 * 32 *  80 * 2);  // 45056
    const int SMGR  = 139264;
    cudaFuncSetAttribute(wmma_gemm<128, 128, 4, 2>,
                         cudaFuncAttributeMaxDynamicSharedMemorySize, SM128);
    cudaFuncSetAttribute(wmma_gemm<64, 128, 2, 2>,
                         cudaFuncAttributeMaxDynamicSharedMemorySize, SM64);
    cudaFuncSetAttribute(wmma_gemm<64, 64, 2, 2>,
                         cudaFuncAttributeMaxDynamicSharedMemorySize, SMKX);
    cudaFuncSetAttribute(gram_argmax_scatter,
                         cudaFuncAttributeMaxDynamicSharedMemorySize, SMGR);

    cudaMemcpyAsync(gX, X, (size_t)Dc * Nc * sizeof(float),
                    cudaMemcpyDeviceToDevice);

    for (int l = 0; l < Lc; l++) {
        const float* Kl  = Kp + (size_t)l * Hc * Qc * Dc;
        const float* Vl  = Vp + (size_t)l * Hc * Dc * Dc;
        const float* W1l = W1 + (size_t)l * DFFc * Dc;
        const float* b1l = b1 + (size_t)l * DFFc;
        const float* W2l = W2 + (size_t)l * Dc * DFFc;
        const float* b2l = b2 + (size_t)l * Dc;

        // 1) KX = K_l @ X   [256,2048], K=512  (128 blocks)
        wmma_gemm<64, 64, 2, 2><<<dim3(Nc / 64, (Hc * Qc) / 64, 1), 128, SMKX>>>(
            Kl, gX, gKX, Hc * Qc, Nc, Dc, 0, 0, nullptr, nullptr, 0);

        // 2) Y[h] = V_lh @ X  (batched over heads)
        wmma_gemm<128, 128, 4, 2><<<dim3(Nc / 128, Dc / 128, Hc), 256, SM128>>>(
            Vl, gX, gY, Dc, Nc, Dc,
            (long long)Dc * Dc, (long long)Dc * Nc, nullptr, nullptr, 0);

        // 3) attn = X
        cudaMemcpyAsync(gAttn, gX, (size_t)Dc * Nc * sizeof(float),
                        cudaMemcpyDeviceToDevice);

        // 4) fused gram+argmax+scatter: attn += sum_h Y[h] @ weights[h]
        gram_argmax_scatter<<<dim3(Nc / 64, Hc), 256, SMGR>>>(gKX, gY, gAttn);

        // 5) ff1 = relu(W1_l @ attn + b1_l)
        wmma_gemm<128, 128, 4, 2><<<dim3(Nc / 128, DFFc / 128, 1), 256, SM128>>>(
            W1l, gAttn, gFF1, DFFc, Nc, Dc, 0, 0, b1l, nullptr, 1);

        // 6) X = attn + W2_l @ ff1 + b2_l
        wmma_gemm<64, 128, 2, 2><<<dim3(Nc / 128, Dc / 64, 1), 128, SM64>>>(
            W2l, gFF1, gX, Dc, Nc, DFFc, 0, 0, b2l, gAttn, 2);
    }

    cudaMemcpyAsync(d_out, gX, (size_t)Dc * Nc * sizeof(float),
                    cudaMemcpyDeviceToDevice);
}

// round 6
// speedup vs baseline: 1.1649x; 1.1649x over previous
#include <cuda_runtime.h>
#include <cuda_bf16.h>
#include <mma.h>
#include <cstdint>

using namespace nvcuda;

#define Lc   8
#define Hc   4
#define Qc   64
#define Dc   512
#define Nc   2048
#define DFFc 2048

// ---------------- device scratch (no allocations allowed) ----------------
__device__ float g_X[Dc * Nc];
__device__ float g_attn[Dc * Nc];
__device__ float g_Y[Hc * Dc * Nc];
__device__ __nv_bfloat16 g_Kh[Lc * Hc * Qc * Dc],  g_Kl[Lc * Hc * Qc * Dc];
__device__ __nv_bfloat16 g_Vh[Lc * Hc * Dc * Dc],  g_Vl[Lc * Hc * Dc * Dc];
__device__ __nv_bfloat16 g_W1h[Lc * DFFc * Dc],    g_W1l[Lc * DFFc * Dc];
__device__ __nv_bfloat16 g_W2h[Lc * Dc * DFFc],    g_W2l[Lc * Dc * DFFc];
__device__ __nv_bfloat16 g_Xh[Dc * Nc],            g_Xl[Dc * Nc];
__device__ __nv_bfloat16 g_Ath[Dc * Nc],           g_Atl[Dc * Nc];
__device__ __nv_bfloat16 g_F1h[DFFc * Nc],         g_F1l[DFFc * Nc];
__device__ __nv_bfloat16 g_KXh[Hc * Qc * Nc],      g_KXl[Hc * Qc * Nc];

// ---------------- helpers --------------------------------------------------
__device__ __forceinline__ uint32_t smem_u32(const void* p) {
    uint32_t a;
    asm("{ .reg .u64 t; cvta.to.shared.u64 t, %1; cvt.u32.u64 %0, t; }"
        : "=r"(a) : "l"(p));
    return a;
}
__device__ __forceinline__ void cp16(void* s, const void* g) {
    asm volatile("cp.async.cg.shared.global [%0], [%1], 16;"
                 :: "r"(smem_u32(s)), "l"(g) : "memory");
}
__device__ __forceinline__ void cp_commit() {
    asm volatile("cp.async.commit_group;" ::: "memory");
}
template<int N> __device__ __forceinline__ void cp_wait() {
    asm volatile("cp.async.wait_group %0;" :: "n"(N) : "memory");
}

__device__ __forceinline__ void split_store4(__nv_bfloat16* __restrict__ Hd,
                                             __nv_bfloat16* __restrict__ Ld,
                                             float4 v)
{
    __nv_bfloat162 h0 = __floats2bfloat162_rn(v.x, v.y);
    __nv_bfloat162 h1 = __floats2bfloat162_rn(v.z, v.w);
    float2 f0 = __bfloat1622float2(h0);
    float2 f1 = __bfloat1622float2(h1);
    __nv_bfloat162 l0 = __floats2bfloat162_rn(v.x - f0.x, v.y - f0.y);
    __nv_bfloat162 l1 = __floats2bfloat162_rn(v.z - f1.x, v.w - f1.y);
    *(__nv_bfloat162*)(Hd)     = h0;
    *(__nv_bfloat162*)(Hd + 2) = h1;
    *(__nv_bfloat162*)(Ld)     = l0;
    *(__nv_bfloat162*)(Ld + 2) = l1;
}

__device__ __forceinline__ unsigned enc_f(float f) {
    unsigned u = __float_as_uint(f);
    return (u & 0x80000000u) ? ~u : (u | 0x80000000u);
}
__device__ __forceinline__ float dec_f(unsigned v) {
    return __uint_as_float((v & 0x80000000u) ? (v ^ 0x80000000u) : ~v);
}

// ---------------- fp32 -> bf16 h/l plane split -----------------------------
__global__ void __launch_bounds__(256) split_kernel(
    const float4* __restrict__ src,
    __nv_bfloat16* __restrict__ h, __nv_bfloat16* __restrict__ l, int n4)
{
    int i = blockIdx.x * 256 + threadIdx.x;
    if (i < n4) split_store4(h + (size_t)i * 4, l + (size_t)i * 4, src[i]);
}

// ============ bf16-plane 3x GEMM with cp.async multistage pipeline ========
// A:[M,K] (h/l planes), B:[K,N] (h/l planes), all row-major bf16.
// mode bits: 1=relu(+bias), 2=residual(+bias), 4=write fp32 C, 8=write planes.
// mode==4 exactly -> fast direct wmma store (no bias/planes).
template<int BM, int BN, int WM, int WN, int S>
__global__ void __launch_bounds__(WM * WN * 32) bf16_gemm(
    const __nv_bfloat16* __restrict__ Ah, const __nv_bfloat16* __restrict__ Al,
    const __nv_bfloat16* __restrict__ Bh, const __nv_bfloat16* __restrict__ Bl,
    float* __restrict__ C,
    __nv_bfloat16* __restrict__ Ch, __nv_bfloat16* __restrict__ Cl,
    int M, int N, int K, long long strideA, long long strideC,
    const float* __restrict__ bias, const float* __restrict__ R, int mode)
{
    constexpr int TH = WM * WN * 32;
    constexpr int BK = 32;
    constexpr int AP = 40;                 // A smem pitch (bf16 elems)
    constexpr int BP = BN + 8;             // B smem pitch
    constexpr int ABYT = BM * AP * 2;
    constexpr int BBYT = BK * BP * 2;
    constexpr int STG = 2 * ABYT + 2 * BBYT;
    constexpr int MF = BM / (WM * 16);
    constexpr int NF = BN / (WN * 16);
    constexpr int AIT = BM * (BK / 8) / TH;
    constexpr int BIT = BK * (BN / 8) / TH;

    extern __shared__ char sm[];
    const int tid = threadIdx.x, w = tid >> 5;
    Ah += (size_t)blockIdx.z * strideA;
    Al += (size_t)blockIdx.z * strideA;
    if (C) C += (size_t)blockIdx.z * strideC;
    const int bm = blockIdx.y * BM;
    const int bn = blockIdx.x * BN;
    const int wm0 = (w % WM) * (MF * 16);
    const int wn0 = (w / WM) * (NF * 16);
    const int KT = K / BK;

    auto issue = [&](int tile) {
        const int k0 = tile * BK;
        char* st = sm + (tile % S) * STG;
        __nv_bfloat16* sAh = (__nv_bfloat16*)st;
        __nv_bfloat16* sAl = (__nv_bfloat16*)(st + ABYT);
        __nv_bfloat16* sBh = (__nv_bfloat16*)(st + 2 * ABYT);
        __nv_bfloat16* sBl = (__nv_bfloat16*)(st + 2 * ABYT + BBYT);
#pragma unroll
        for (int p = 0; p < AIT; p++) {
            const int c = tid + p * TH;
            const int r = c >> 2, c8 = (c & 3) * 8;
            cp16(sAh + r * AP + c8, Ah + (size_t)(bm + r) * K + k0 + c8);
            cp16(sAl + r * AP + c8, Al + (size_t)(bm + r) * K + k0 + c8);
        }
#pragma unroll
        for (int p = 0; p < BIT; p++) {
            const int c = tid + p * TH;
            const int r = c / (BN / 8), c8 = (c % (BN / 8)) * 8;
            cp16(sBh + r * BP + c8, Bh + (size_t)(k0 + r) * N + bn + c8);
            cp16(sBl + r * BP + c8, Bl + (size_t)(k0 + r) * N + bn + c8);
        }
    };

    wmma::fragment<wmma::accumulator, 16, 16, 16, float> acc[MF][NF];
#pragma unroll
    for (int i = 0; i < MF; i++)
#pragma unroll
        for (int j = 0; j < NF; j++) wmma::fill_fragment(acc[i][j], 0.f);

    // prologue: S-1 stages in flight
#pragma unroll
    for (int t = 0; t < S - 1; t++) {
        if (t < KT) issue(t);
        cp_commit();
    }

#pragma unroll 1
    for (int kt = 0; kt < KT; kt++) {
        if (kt + S - 1 < KT) issue(kt + S - 1);
        cp_commit();
        cp_wait<S - 1>();
        __syncthreads();

        char* st = sm + (kt % S) * STG;
        const __nv_bfloat16* sAh = (const __nv_bfloat16*)st;
        const __nv_bfloat16* sAl = (const __nv_bfloat16*)(st + ABYT);
        const __nv_bfloat16* sBh = (const __nv_bfloat16*)(st + 2 * ABYT);
        const __nv_bfloat16* sBl = (const __nv_bfloat16*)(st + 2 * ABYT + BBYT);

#pragma unroll
        for (int kks = 0; kks < 2; kks++) {
            const int kk = kks * 16;
            wmma::fragment<wmma::matrix_a, 16, 16, 16, __nv_bfloat16, wmma::row_major> fAh[MF];
            wmma::fragment<wmma::matrix_b, 16, 16, 16, __nv_bfloat16, wmma::row_major> fBh[NF];
#pragma unroll
            for (int i = 0; i < MF; i++)
                wmma::load_matrix_sync(fAh[i], sAh + (wm0 + i * 16) * AP + kk, AP);
#pragma unroll
            for (int j = 0; j < NF; j++)
                wmma::load_matrix_sync(fBh[j], sBh + kk * BP + wn0 + j * 16, BP);
            // product 1: Ah*Bh — 8 independent MMAs
#pragma unroll
            for (int i = 0; i < MF; i++)
#pragma unroll
                for (int j = 0; j < NF; j++)
                    wmma::mma_sync(acc[i][j], fAh[i], fBh[j], acc[i][j]);
            // product 2: Ah*Bl
            {
                wmma::fragment<wmma::matrix_b, 16, 16, 16, __nv_bfloat16, wmma::row_major> fBl[NF];
#pragma unroll
                for (int j = 0; j < NF; j++)
                    wmma::load_matrix_sync(fBl[j], sBl + kk * BP + wn0 + j * 16, BP);
#pragma unroll
                for (int i = 0; i < MF; i++)
#pragma unroll
                    for (int j = 0; j < NF; j++)
                        wmma::mma_sync(acc[i][j], fAh[i], fBl[j], acc[i][j]);
            }
            // product 3: Al*Bh
            {
                wmma::fragment<wmma::matrix_a, 16, 16, 16, __nv_bfloat16, wmma::row_major> fAl[MF];
#pragma unroll
                for (int i = 0; i < MF; i++)
                    wmma::load_matrix_sync(fAl[i], sAl + (wm0 + i * 16) * AP + kk, AP);
#pragma unroll
                for (int i = 0; i < MF; i++)
#pragma unroll
                    for (int j = 0; j < NF; j++)
                        wmma::mma_sync(acc[i][j], fAl[i], fBh[j], acc[i][j]);
            }
        }
        __syncthreads();
    }

    if (mode == 4) {
#pragma unroll
        for (int i = 0; i < MF; i++)
#pragma unroll
            for (int j = 0; j < NF; j++)
                wmma::store_matrix_sync(
                    &C[(size_t)(bm + wm0 + i * 16) * N + bn + wn0 + j * 16],
                    acc[i][j], N, wmma::mem_row_major);
        return;
    }

    // staged epilogue
    float* cs = (float*)sm;
#pragma unroll
    for (int i = 0; i < MF; i++)
#pragma unroll
        for (int j = 0; j < NF; j++)
            wmma::store_matrix_sync(cs + (size_t)(wm0 + i * 16) * BN + wn0 + j * 16,
                                    acc[i][j], BN, wmma::mem_row_major);
    __syncthreads();

    constexpr int CIT = BM * BN / 4 / TH;
#pragma unroll
    for (int p = 0; p < CIT; p++) {
        const int id = tid + p * TH;
        const int row = id / (BN / 4), c4 = id % (BN / 4);
        float4 v = ((const float4*)cs)[id];
        const int gr = bm + row;
        const int gc = bn + c4 * 4;
        if (mode & 3) {
            const float bv = bias[gr];
            v.x += bv; v.y += bv; v.z += bv; v.w += bv;
        }
        if (mode & 1) {
            v.x = fmaxf(v.x, 0.f); v.y = fmaxf(v.y, 0.f);
            v.z = fmaxf(v.z, 0.f); v.w = fmaxf(v.w, 0.f);
        }
        if (mode & 2) {
            float4 r4 = *(const float4*)&R[(size_t)gr * N + gc];
            v.x += r4.x; v.y += r4.y; v.z += r4.z; v.w += r4.w;
        }
        if (mode & 4) *(float4*)&C[(size_t)gr * N + gc] = v;
        if (mode & 8) split_store4(Ch + (size_t)gr * N + gc,
                                   Cl + (size_t)gr * N + gc, v);
    }
}

// ====== fused gram + argmax + scatter (bf16 planes, cp.async 2-stage) ======
#define CAND 96
__global__ void __launch_bounds__(256) gram_argmax_scatter(
    const __nv_bfloat16* __restrict__ KXh, const __nv_bfloat16* __restrict__ KXl,
    const float* __restrict__ Y, float* __restrict__ attn)
{
    constexpr int AP = 72, BP = 136, CP = 132;
    extern __shared__ char sm[];
    __nv_bfloat16* aH = (__nv_bfloat16*)sm;                 // 9216
    __nv_bfloat16* aL = (__nv_bfloat16*)(sm + 9216);        // 9216
    // B stages at 18432 .. 88064 (2 stages x (bH 17408 + bL 17408))
    float*    Cs   = (float*)(sm + 88064);                  // 33792
    unsigned* rm   = (unsigned*)(sm + 121856);
    int*      cnt  = (int*)(sm + 122112);
    float*    wrow = (float*)(sm + 122368);
    int*      cm   = (int*)(sm + 122624);                   // 24576
    float*    csv  = (float*)(sm + 147200);                 // 24576 -> 171776

    const int h  = blockIdx.y;
    const int r0 = blockIdx.x * 64;
    const __nv_bfloat16* Ahg = KXh + (size_t)h * Qc * Nc;
    const __nv_bfloat16* Alg = KXl + (size_t)h * Qc * Nc;
    const int tid = threadIdx.x, w = tid >> 5, lane = tid & 31;
    const int wm0 = (w & 1) * 32, wn0 = (w >> 1) * 32;

    if (tid < 64) { rm[tid] = enc_f(-1e30f); cnt[tid] = 0; }

    auto issueB = [&](int mt, int s) {
        const int m0 = mt * 128;
        __nv_bfloat16* bH = (__nv_bfloat16*)(sm + 18432 + s * 34816);
        __nv_bfloat16* bL = (__nv_bfloat16*)(sm + 18432 + s * 34816 + 17408);
#pragma unroll
        for (int p = 0; p < 4; p++) {
            const int c = tid + p * 256;
            const int q = c >> 4, c8 = (c & 15) * 8;
            cp16(bH + q * BP + c8, Ahg + (size_t)q * Nc + m0 + c8);
            cp16(bL + q * BP + c8, Alg + (size_t)q * Nc + m0 + c8);
        }
    };

    // A stripe (64 q-rows x 64 cols) + B tile 0 in group 0
#pragma unroll
    for (int p = 0; p < 2; p++) {
        const int c = tid + p * 256;
        const int q = c >> 3, c8 = (c & 7) * 8;
        cp16(aH + q * AP + c8, Ahg + (size_t)q * Nc + r0 + c8);
        cp16(aL + q * AP + c8, Alg + (size_t)q * Nc + r0 + c8);
    }
    issueB(0, 0);
    cp_commit();

    for (int mt = 0; mt < Nc / 128; mt++) {
        if (mt + 1 < Nc / 128) issueB(mt + 1, (mt + 1) & 1);
        cp_commit();
        cp_wait<1>();
        __syncthreads();

        const __nv_bfloat16* bH = (const __nv_bfloat16*)(sm + 18432 + (mt & 1) * 34816);
        const __nv_bfloat16* bL = (const __nv_bfloat16*)(sm + 18432 + (mt & 1) * 34816 + 17408);

        wmma::fragment<wmma::accumulator, 16, 16, 16, float> acc[2][2];
#pragma unroll
        for (int i = 0; i < 2; i++)
#pragma unroll
            for (int j = 0; j < 2; j++) wmma::fill_fragment(acc[i][j], 0.f);

#pragma unroll
        for (int kks = 0; kks < 4; kks++) {
            const int kk = kks * 16;
            wmma::fragment<wmma::matrix_a, 16, 16, 16, __nv_bfloat16, wmma::col_major> fAh[2];
            wmma::fragment<wmma::matrix_b, 16, 16, 16, __nv_bfloat16, wmma::row_major> fBh[2];
#pragma unroll
            for (int i = 0; i < 2; i++)
                wmma::load_matrix_sync(fAh[i], aH + kk * AP + wm0 + i * 16, AP);
#pragma unroll
            for (int j = 0; j < 2; j++)
                wmma::load_matrix_sync(fBh[j], bH + kk * BP + wn0 + j * 16, BP);
#pragma unroll
            for (int i = 0; i < 2; i++)
#pragma unroll
                for (int j = 0; j < 2; j++)
                    wmma::mma_sync(acc[i][j], fAh[i], fBh[j], acc[i][j]);
            {
                wmma::fragment<wmma::matrix_b, 16, 16, 16, __nv_bfloat16, wmma::row_major> fBl[2];
#pragma unroll
                for (int j = 0; j < 2; j++)
                    wmma::load_matrix_sync(fBl[j], bL + kk * BP + wn0 + j * 16, BP);
#pragma unroll
                for (int i = 0; i < 2; i++)
#pragma unroll
                    for (int j = 0; j < 2; j++)
                        wmma::mma_sync(acc[i][j], fAh[i], fBl[j], acc[i][j]);
            }
            {
                wmma::fragment<wmma::matrix_a, 16, 16, 16, __nv_bfloat16, wmma::col_major> fAl[2];
#pragma unroll
                for (int i = 0; i < 2; i++)
                    wmma::load_matrix_sync(fAl[i], aL + kk * AP + wm0 + i * 16, AP);
#pragma unroll
                for (int i = 0; i < 2; i++)
#pragma unroll
                    for (int j = 0; j < 2; j++)
                        wmma::mma_sync(acc[i][j], fAl[i], fBh[j], acc[i][j]);
            }
        }
#pragma unroll
        for (int i = 0; i < 2; i++)
#pragma unroll
            for (int j = 0; j < 2; j++)
                wmma::store_matrix_sync(Cs + (wm0 + i * 16) * CP + wn0 + j * 16,
                                        acc[i][j], CP, wmma::mem_row_major);
        __syncthreads();

        // per-row tile max -> merge into running max
        const int r = tid >> 2;
        const int c0 = (tid & 3) * 32;
        float tm = -1e30f;
#pragma unroll
        for (int c = 0; c < 32; c++) tm = fmaxf(tm, Cs[r * CP + c0 + c]);
        tm = fmaxf(tm, __shfl_xor_sync(0xffffffffu, tm, 1, 4));
        tm = fmaxf(tm, __shfl_xor_sync(0xffffffffu, tm, 2, 4));
        if ((tid & 3) == 0) atomicMax(&rm[r], enc_f(tm));
        __syncthreads();

        const float thr = dec_f(rm[r]) - 0.5f;
        const int m0 = mt * 128;
#pragma unroll
        for (int c = 0; c < 32; c++) {
            const float v = Cs[r * CP + c0 + c];
            if (v >= thr) {
                int pos = atomicAdd(&cnt[r], 1);
                if (pos < CAND) {
                    cm[r * CAND + pos]  = m0 + c0 + c;
                    csv[r * CAND + pos] = v;
                }
            }
        }
        __syncthreads();
    }

    // finalize: filter candidates by final max
    if (tid < 64) {
        const float fmax = dec_f(rm[tid]);
        const float thrF = fmax - 0.5f;
        const int nc = cnt[tid] < CAND ? cnt[tid] : CAND;
        int hits = 0;
        for (int j = 0; j < nc; j++) {
            if (csv[tid * CAND + j] >= thrF) {
                cm[tid * CAND + hits] = cm[tid * CAND + j];
                hits++;
            }
        }
        cnt[tid] = hits;
        wrow[tid] = (fabsf(fmax) > 0.5f && hits > 0) ? 1.f / (float)hits : 0.f;
    }
    __syncthreads();

    // scatter: warp-per-row, no block syncs
    const float* Yh = Y + (size_t)h * Dc * Nc;
    for (int rr = 0; rr < 8; rr++) {
        const int r = w * 8 + rr;
        const float wv = wrow[r];
        const int hits = cnt[r];
        if (wv == 0.f || hits == 0) continue;
        const int n = r0 + r;
        float yv[16];
#pragma unroll
        for (int p = 0; p < 16; p++)
            yv[p] = wv * Yh[(size_t)(lane + p * 32) * Nc + n];
        for (int j = 0; j < hits; j++) {
            const int m = cm[r * CAND + j];
#pragma unroll
            for (int p = 0; p < 16; p++)
                atomicAdd(&attn[(size_t)(lane + p * 32) * Nc + m], yv[p]);
        }
    }
}

// --------------------------------------------------------------------------
extern "C" void kernel_launch(void* const* d_in, const int* in_sizes, int n_in,
                              void* d_out, int out_size)
{
    const float* X  = (const float*)d_in[0];
    const float* Kp = (const float*)d_in[1];
    const float* Vp = (const float*)d_in[2];
    const float* W1 = (const float*)d_in[3];
    const float* b1 = (const float*)d_in[4];
    const float* W2 = (const float*)d_in[5];
    const float* b2 = (const float*)d_in[6];

    float *gX, *gAttn, *gY;
    __nv_bfloat16 *gKh, *gKl, *gVh, *gVl, *gW1h, *gW1l, *gW2h, *gW2l;
    __nv_bfloat16 *gXh, *gXl, *gAth, *gAtl, *gF1h, *gF1l, *gKXh, *gKXl;
    cudaGetSymbolAddress((void**)&gX,   g_X);
    cudaGetSymbolAddress((void**)&gAttn,g_attn);
    cudaGetSymbolAddress((void**)&gY,   g_Y);
    cudaGetSymbolAddress((void**)&gKh,  g_Kh);   cudaGetSymbolAddress((void**)&gKl,  g_Kl);
    cudaGetSymbolAddress((void**)&gVh,  g_Vh);   cudaGetSymbolAddress((void**)&gVl,  g_Vl);
    cudaGetSymbolAddress((void**)&gW1h, g_W1h);  cudaGetSymbolAddress((void**)&gW1l, g_W1l);
    cudaGetSymbolAddress((void**)&gW2h, g_W2h);  cudaGetSymbolAddress((void**)&gW2l, g_W2l);
    cudaGetSymbolAddress((void**)&gXh,  g_Xh);   cudaGetSymbolAddress((void**)&gXl,  g_Xl);
    cudaGetSymbolAddress((void**)&gAth, g_Ath);  cudaGetSymbolAddress((void**)&gAtl, g_Atl);
    cudaGetSymbolAddress((void**)&gF1h, g_F1h);  cudaGetSymbolAddress((void**)&gF1l, g_F1l);
    cudaGetSymbolAddress((void**)&gKXh, g_KXh);  cudaGetSymbolAddress((void**)&gKXl, g_KXl);

    // dynamic smem sizes
    const int SMY  = 4 * (2 * 128 * 40 * 2 + 2 * 32 * 136 * 2);   // 151552
    const int SMF2 = 4 * (2 *  64 * 40 * 2 + 2 * 32 * 136 * 2);   // 110592
    const int SMKX = 4 * (2 *  64 * 40 * 2 + 2 * 32 *  72 * 2);   // 77824
    const int SMGR = 171776;
    cudaFuncSetAttribute(bf16_gemm<128, 128, 4, 2, 4>,
                         cudaFuncAttributeMaxDynamicSharedMemorySize, SMY);
    cudaFuncSetAttribute(bf16_gemm<64, 128, 2, 2, 4>,
                         cudaFuncAttributeMaxDynamicSharedMemorySize, SMF2);
    cudaFuncSetAttribute(bf16_gemm<64, 64, 2, 2, 4>,
                         cudaFuncAttributeMaxDynamicSharedMemorySize, SMKX);
    cudaFuncSetAttribute(gram_argmax_scatter,
                         cudaFuncAttributeMaxDynamicSharedMemorySize, SMGR);

    // split all weights + initial X into bf16 h/l planes
    {
        const int nK  = Lc * Hc * Qc * Dc / 4;
        const int nV  = Lc * Hc * Dc * Dc / 4;
        const int nW  = Lc * DFFc * Dc / 4;
        const int nX  = Dc * Nc / 4;
        split_kernel<<<(nK + 255) / 256, 256>>>((const float4*)Kp, gKh, gKl, nK);
        split_kernel<<<(nV + 255) / 256, 256>>>((const float4*)Vp, gVh, gVl, nV);
        split_kernel<<<(nW + 255) / 256, 256>>>((const float4*)W1, gW1h, gW1l, nW);
        split_kernel<<<(nW + 255) / 256, 256>>>((const float4*)W2, gW2h, gW2l, nW);
        split_kernel<<<(nX + 255) / 256, 256>>>((const float4*)X,  gXh,  gXl,  nX);
    }
    cudaMemcpyAsync(gX, X, (size_t)Dc * Nc * sizeof(float),
                    cudaMemcpyDeviceToDevice);

    for (int l = 0; l < Lc; l++) {
        const float* b1l = b1 + (size_t)l * DFFc;
        const float* b2l = b2 + (size_t)l * Dc;

        // 1) KX planes = K_l @ X   [256,2048], K=512 -> mode 8 (planes only)
        bf16_gemm<64, 64, 2, 2, 4><<<dim3(Nc / 64, (Hc * Qc) / 64, 1), 128, SMKX>>>(
            gKh + (size_t)l * Hc * Qc * Dc, gKl + (size_t)l * Hc * Qc * Dc,
            gXh, gXl, nullptr, gKXh, gKXl,
            Hc * Qc, Nc, Dc, 0, 0, nullptr, nullptr, 8);

        // 2) Y[h] = V_lh @ X (batched) -> fp32 direct (mode 4)
        bf16_gemm<128, 128, 4, 2, 4><<<dim3(Nc / 128, Dc / 128, Hc), 256, SMY>>>(
            gVh + (size_t)l * Hc * Dc * Dc, gVl + (size_t)l * Hc * Dc * Dc,
            gXh, gXl, gY, nullptr, nullptr,
            Dc, Nc, Dc, (long long)Dc * Dc, (long long)Dc * Nc,
            nullptr, nullptr, 4);

        // 3) attn = X
        cudaMemcpyAsync(gAttn, gX, (size_t)Dc * Nc * sizeof(float),
                        cudaMemcpyDeviceToDevice);

        // 4) fused gram+argmax+scatter
        gram_argmax_scatter<<<dim3(Nc / 64, Hc), 256, SMGR>>>(gKXh, gKXl, gY, gAttn);

        // 5) attn planes (for FF1 B operand)
        split_kernel<<<(Dc * Nc / 4 + 255) / 256, 256>>>(
            (const float4*)gAttn, gAth, gAtl, Dc * Nc / 4);

        // 6) ff1 planes = relu(W1_l @ attn + b1)  -> mode 9 (relu|planes)
        bf16_gemm<128, 128, 4, 2, 4><<<dim3(Nc / 128, DFFc / 128, 1), 256, SMY>>>(
            gW1h + (size_t)l * DFFc * Dc, gW1l + (size_t)l * DFFc * Dc,
            gAth, gAtl, nullptr, gF1h, gF1l,
            DFFc, Nc, Dc, 0, 0, b1l, nullptr, 9);

        // 7) X = attn + W2_l @ ff1 + b2 -> mode 14 (res|fp32|planes)
        bf16_gemm<64, 128, 2, 2, 4><<<dim3(Nc / 128, Dc / 64, 1), 128, SMF2>>>(
            gW2h + (size_t)l * Dc * DFFc, gW2l + (size_t)l * Dc * DFFc,
            gF1h, gF1l, gX, gXh, gXl,
            Dc, Nc, DFFc, 0, 0, b2l, gAttn, 14);
    }

    cudaMemcpyAsync(d_out, gX, (size_t)Dc * Nc * sizeof(float),
                    cudaMemcpyDeviceToDevice);
}

// round 8
// speedup vs baseline: 1.2173x; 1.0450x over previous
#include <cuda_runtime.h>
#include <cuda_bf16.h>
#include <mma.h>
#include <cstdint>

using namespace nvcuda;

#define Lc   8
#define Hc   4
#define Qc   64
#define Dc   512
#define Nc   2048
#define DFFc 2048

// ---------------- device scratch (no allocations allowed) ----------------
__device__ float g_X[Dc * Nc];
__device__ float g_attn[Dc * Nc];
__device__ float g_Y[Hc * Dc * Nc];
__device__ __nv_bfloat16 g_Kh[Lc * Hc * Qc * Dc],  g_Kl[Lc * Hc * Qc * Dc];
__device__ __nv_bfloat16 g_Vh[Lc * Hc * Dc * Dc],  g_Vl[Lc * Hc * Dc * Dc];
__device__ __nv_bfloat16 g_W1h[Lc * DFFc * Dc],    g_W1l[Lc * DFFc * Dc];
__device__ __nv_bfloat16 g_W2h[Lc * Dc * DFFc],    g_W2l[Lc * Dc * DFFc];
__device__ __nv_bfloat16 g_Xh[Dc * Nc],            g_Xl[Dc * Nc];
__device__ __nv_bfloat16 g_Ath[Dc * Nc],           g_Atl[Dc * Nc];
__device__ __nv_bfloat16 g_F1h[DFFc * Nc],         g_F1l[DFFc * Nc];
__device__ __nv_bfloat16 g_KXh[Hc * Qc * Nc],      g_KXl[Hc * Qc * Nc];

// ---------------- helpers --------------------------------------------------
__device__ __forceinline__ uint32_t smem_u32(const void* p) {
    uint32_t a;
    asm("{ .reg .u64 t; cvta.to.shared.u64 t, %1; cvt.u32.u64 %0, t; }"
        : "=r"(a) : "l"(p));
    return a;
}
__device__ __forceinline__ void cp16(void* s, const void* g) {
    asm volatile("cp.async.cg.shared.global [%0], [%1], 16;"
                 :: "r"(smem_u32(s)), "l"(g) : "memory");
}
__device__ __forceinline__ void cp_commit() {
    asm volatile("cp.async.commit_group;" ::: "memory");
}
template<int N> __device__ __forceinline__ void cp_wait() {
    asm volatile("cp.async.wait_group %0;" :: "n"(N) : "memory");
}

__device__ __forceinline__ void split_store4(__nv_bfloat16* __restrict__ Hd,
                                             __nv_bfloat16* __restrict__ Ld,
                                             float4 v)
{
    __nv_bfloat162 h0 = __floats2bfloat162_rn(v.x, v.y);
    __nv_bfloat162 h1 = __floats2bfloat162_rn(v.z, v.w);
    float2 f0 = __bfloat1622float2(h0);
    float2 f1 = __bfloat1622float2(h1);
    __nv_bfloat162 l0 = __floats2bfloat162_rn(v.x - f0.x, v.y - f0.y);
    __nv_bfloat162 l1 = __floats2bfloat162_rn(v.z - f1.x, v.w - f1.y);
    *(__nv_bfloat162*)(Hd)     = h0;
    *(__nv_bfloat162*)(Hd + 2) = h1;
    *(__nv_bfloat162*)(Ld)     = l0;
    *(__nv_bfloat162*)(Ld + 2) = l1;
}

__device__ __forceinline__ unsigned enc_f(float f) {
    unsigned u = __float_as_uint(f);
    return (u & 0x80000000u) ? ~u : (u | 0x80000000u);
}
__device__ __forceinline__ float dec_f(unsigned v) {
    return __uint_as_float((v & 0x80000000u) ? (v ^ 0x80000000u) : ~v);
}

// ---------------- fp32 -> bf16 h/l plane split -----------------------------
__global__ void __launch_bounds__(256) split_kernel(
    const float4* __restrict__ src,
    __nv_bfloat16* __restrict__ h, __nv_bfloat16* __restrict__ l, int n4)
{
    int i = blockIdx.x * 256 + threadIdx.x;
    if (i < n4) split_store4(h + (size_t)i * 4, l + (size_t)i * 4, src[i]);
}

// ============ bf16-plane 3x GEMM with cp.async multistage pipeline ========
// A:[M,K] (h/l planes), B:[K,N] (h/l planes), all row-major bf16.
// mode bits: 1=relu(+bias), 2=residual(+bias), 4=write fp32 C,
//            8=write h+l planes.
// mode==4 exactly -> direct wmma store.
template<int BM, int BN, int WM, int WN, int S>
__global__ void __launch_bounds__(WM * WN * 32) bf16_gemm(
    const __nv_bfloat16* __restrict__ Ah, const __nv_bfloat16* __restrict__ Al,
    const __nv_bfloat16* __restrict__ Bh, const __nv_bfloat16* __restrict__ Bl,
    float* __restrict__ C,
    __nv_bfloat16* __restrict__ Ch, __nv_bfloat16* __restrict__ Cl,
    int M, int N, int K, long long strideA, long long strideC,
    const float* __restrict__ bias, const float* __restrict__ R, int mode)
{
    constexpr int TH = WM * WN * 32;
    constexpr int BK = 32;
    constexpr int AP = 40;
    constexpr int BP = BN + 8;
    constexpr int ABYT = BM * AP * 2;
    constexpr int BBYT = BK * BP * 2;
    constexpr int STG = 2 * ABYT + 2 * BBYT;
    constexpr int MF = BM / (WM * 16);
    constexpr int NF = BN / (WN * 16);
    constexpr int AIT = BM * (BK / 8) / TH;
    constexpr int BIT = BK * (BN / 8) / TH;

    extern __shared__ char sm[];
    const int tid = threadIdx.x, w = tid >> 5;
    Ah += (size_t)blockIdx.z * strideA;
    Al += (size_t)blockIdx.z * strideA;
    if (C) C += (size_t)blockIdx.z * strideC;
    const int bm = blockIdx.y * BM;
    const int bn = blockIdx.x * BN;
    const int wm0 = (w % WM) * (MF * 16);
    const int wn0 = (w / WM) * (NF * 16);
    const int KT = K / BK;

    auto issue = [&](int tile) {
        const int k0 = tile * BK;
        char* st = sm + (tile % S) * STG;
        __nv_bfloat16* sAh = (__nv_bfloat16*)st;
        __nv_bfloat16* sAl = (__nv_bfloat16*)(st + ABYT);
        __nv_bfloat16* sBh = (__nv_bfloat16*)(st + 2 * ABYT);
        __nv_bfloat16* sBl = (__nv_bfloat16*)(st + 2 * ABYT + BBYT);
#pragma unroll
        for (int p = 0; p < AIT; p++) {
            const int c = tid + p * TH;
            const int r = c >> 2, c8 = (c & 3) * 8;
            cp16(sAh + r * AP + c8, Ah + (size_t)(bm + r) * K + k0 + c8);
            cp16(sAl + r * AP + c8, Al + (size_t)(bm + r) * K + k0 + c8);
        }
#pragma unroll
        for (int p = 0; p < BIT; p++) {
            const int c = tid + p * TH;
            const int r = c / (BN / 8), c8 = (c % (BN / 8)) * 8;
            cp16(sBh + r * BP + c8, Bh + (size_t)(k0 + r) * N + bn + c8);
            cp16(sBl + r * BP + c8, Bl + (size_t)(k0 + r) * N + bn + c8);
        }
    };

    wmma::fragment<wmma::accumulator, 16, 16, 16, float> acc[MF][NF];
#pragma unroll
    for (int i = 0; i < MF; i++)
#pragma unroll
        for (int j = 0; j < NF; j++) wmma::fill_fragment(acc[i][j], 0.f);

#pragma unroll
    for (int t = 0; t < S - 1; t++) {
        if (t < KT) issue(t);
        cp_commit();
    }

#pragma unroll 1
    for (int kt = 0; kt < KT; kt++) {
        cp_wait<S - 2>();
        __syncthreads();
        if (kt + S - 1 < KT) issue(kt + S - 1);
        cp_commit();

        char* st = sm + (kt % S) * STG;
        const __nv_bfloat16* sAh = (const __nv_bfloat16*)st;
        const __nv_bfloat16* sAl = (const __nv_bfloat16*)(st + ABYT);
        const __nv_bfloat16* sBh = (const __nv_bfloat16*)(st + 2 * ABYT);
        const __nv_bfloat16* sBl = (const __nv_bfloat16*)(st + 2 * ABYT + BBYT);

#pragma unroll
        for (int kks = 0; kks < 2; kks++) {
            const int kk = kks * 16;
            wmma::fragment<wmma::matrix_a, 16, 16, 16, __nv_bfloat16, wmma::row_major> fAh[MF];
            wmma::fragment<wmma::matrix_b, 16, 16, 16, __nv_bfloat16, wmma::row_major> fBh[NF];
#pragma unroll
            for (int i = 0; i < MF; i++)
                wmma::load_matrix_sync(fAh[i], sAh + (wm0 + i * 16) * AP + kk, AP);
#pragma unroll
            for (int j = 0; j < NF; j++)
                wmma::load_matrix_sync(fBh[j], sBh + kk * BP + wn0 + j * 16, BP);
#pragma unroll
            for (int i = 0; i < MF; i++)
#pragma unroll
                for (int j = 0; j < NF; j++)
                    wmma::mma_sync(acc[i][j], fAh[i], fBh[j], acc[i][j]);
            {
                wmma::fragment<wmma::matrix_b, 16, 16, 16, __nv_bfloat16, wmma::row_major> fBl[NF];
#pragma unroll
                for (int j = 0; j < NF; j++)
                    wmma::load_matrix_sync(fBl[j], sBl + kk * BP + wn0 + j * 16, BP);
#pragma unroll
                for (int i = 0; i < MF; i++)
#pragma unroll
                    for (int j = 0; j < NF; j++)
                        wmma::mma_sync(acc[i][j], fAh[i], fBl[j], acc[i][j]);
            }
            {
                wmma::fragment<wmma::matrix_a, 16, 16, 16, __nv_bfloat16, wmma::row_major> fAl[MF];
#pragma unroll
                for (int i = 0; i < MF; i++)
                    wmma::load_matrix_sync(fAl[i], sAl + (wm0 + i * 16) * AP + kk, AP);
#pragma unroll
                for (int i = 0; i < MF; i++)
#pragma unroll
                    for (int j = 0; j < NF; j++)
                        wmma::mma_sync(acc[i][j], fAl[i], fBh[j], acc[i][j]);
            }
        }
    }

    if (mode == 4) {
#pragma unroll
        for (int i = 0; i < MF; i++)
#pragma unroll
            for (int j = 0; j < NF; j++)
                wmma::store_matrix_sync(
                    &C[(size_t)(bm + wm0 + i * 16) * N + bn + wn0 + j * 16],
                    acc[i][j], N, wmma::mem_row_major);
        return;
    }

    __syncthreads();
    float* cs = (float*)sm;
#pragma unroll
    for (int i = 0; i < MF; i++)
#pragma unroll
        for (int j = 0; j < NF; j++)
            wmma::store_matrix_sync(cs + (size_t)(wm0 + i * 16) * BN + wn0 + j * 16,
                                    acc[i][j], BN, wmma::mem_row_major);
    __syncthreads();

    constexpr int CIT = BM * BN / 4 / TH;
#pragma unroll
    for (int p = 0; p < CIT; p++) {
        const int id = tid + p * TH;
        const int row = id / (BN / 4), c4 = id % (BN / 4);
        float4 v = ((const float4*)cs)[id];
        const int gr = bm + row;
        const int gc = bn + c4 * 4;
        if (mode & 3) {
            const float bv = bias[gr];
            v.x += bv; v.y += bv; v.z += bv; v.w += bv;
        }
        if (mode & 1) {
            v.x = fmaxf(v.x, 0.f); v.y = fmaxf(v.y, 0.f);
            v.z = fmaxf(v.z, 0.f); v.w = fmaxf(v.w, 0.f);
        }
        if (mode & 2) {
            float4 r4 = *(const float4*)&R[(size_t)gr * N + gc];
            v.x += r4.x; v.y += r4.y; v.z += r4.z; v.w += r4.w;
        }
        if (mode & 4) *(float4*)&C[(size_t)gr * N + gc] = v;
        if (mode & 8) split_store4(Ch + (size_t)gr * N + gc,
                                   Cl + (size_t)gr * N + gc, v);
    }
}

// ====== fused gram + argmax + scatter (bf16 planes, 3-product, R6-proven) ==
#define CAND 96
__global__ void __launch_bounds__(256) gram_argmax_scatter(
    const __nv_bfloat16* __restrict__ KXh, const __nv_bfloat16* __restrict__ KXl,
    const float* __restrict__ Y, float* __restrict__ attn)
{
    constexpr int AP = 72, BP = 136, CP = 132;
    extern __shared__ char sm[];
    __nv_bfloat16* aH = (__nv_bfloat16*)sm;                 // 9216
    __nv_bfloat16* aL = (__nv_bfloat16*)(sm + 9216);        // 9216
    // B stages at 18432 .. 88064 (2 stages x (bH 17408 + bL 17408))
    float*    Cs   = (float*)(sm + 88064);                  // 33792
    unsigned* rm   = (unsigned*)(sm + 121856);
    int*      cnt  = (int*)(sm + 122112);
    float*    wrow = (float*)(sm + 122368);
    int*      cm   = (int*)(sm + 122624);                   // 24576
    float*    csv  = (float*)(sm + 147200);                 // 24576 -> 171776

    const int h  = blockIdx.y;
    const int r0 = blockIdx.x * 64;
    const __nv_bfloat16* Ahg = KXh + (size_t)h * Qc * Nc;
    const __nv_bfloat16* Alg = KXl + (size_t)h * Qc * Nc;
    const int tid = threadIdx.x, w = tid >> 5, lane = tid & 31;
    const int wm0 = (w & 1) * 32, wn0 = (w >> 1) * 32;

    if (tid < 64) { rm[tid] = enc_f(-1e30f); cnt[tid] = 0; }

    auto issueB = [&](int mt, int s) {
        const int m0 = mt * 128;
        __nv_bfloat16* bH = (__nv_bfloat16*)(sm + 18432 + s * 34816);
        __nv_bfloat16* bL = (__nv_bfloat16*)(sm + 18432 + s * 34816 + 17408);
#pragma unroll
        for (int p = 0; p < 4; p++) {
            const int c = tid + p * 256;
            const int q = c >> 4, c8 = (c & 15) * 8;
            cp16(bH + q * BP + c8, Ahg + (size_t)q * Nc + m0 + c8);
            cp16(bL + q * BP + c8, Alg + (size_t)q * Nc + m0 + c8);
        }
    };

    // A stripe (64 q-rows x 64 cols)
#pragma unroll
    for (int p = 0; p < 2; p++) {
        const int c = tid + p * 256;
        const int q = c >> 3, c8 = (c & 7) * 8;
        cp16(aH + q * AP + c8, Ahg + (size_t)q * Nc + r0 + c8);
        cp16(aL + q * AP + c8, Alg + (size_t)q * Nc + r0 + c8);
    }
    issueB(0, 0);
    cp_commit();

    for (int mt = 0; mt < Nc / 128; mt++) {
        if (mt + 1 < Nc / 128) issueB(mt + 1, (mt + 1) & 1);
        cp_commit();
        cp_wait<1>();
        __syncthreads();

        const __nv_bfloat16* bH = (const __nv_bfloat16*)(sm + 18432 + (mt & 1) * 34816);
        const __nv_bfloat16* bL = (const __nv_bfloat16*)(sm + 18432 + (mt & 1) * 34816 + 17408);

        wmma::fragment<wmma::accumulator, 16, 16, 16, float> acc[2][2];
#pragma unroll
        for (int i = 0; i < 2; i++)
#pragma unroll
            for (int j = 0; j < 2; j++) wmma::fill_fragment(acc[i][j], 0.f);

#pragma unroll
        for (int kks = 0; kks < 4; kks++) {
            const int kk = kks * 16;
            wmma::fragment<wmma::matrix_a, 16, 16, 16, __nv_bfloat16, wmma::col_major> fAh[2];
            wmma::fragment<wmma::matrix_b, 16, 16, 16, __nv_bfloat16, wmma::row_major> fBh[2];
#pragma unroll
            for (int i = 0; i < 2; i++)
                wmma::load_matrix_sync(fAh[i], aH + kk * AP + wm0 + i * 16, AP);
#pragma unroll
            for (int j = 0; j < 2; j++)
                wmma::load_matrix_sync(fBh[j], bH + kk * BP + wn0 + j * 16, BP);
#pragma unroll
            for (int i = 0; i < 2; i++)
#pragma unroll
                for (int j = 0; j < 2; j++)
                    wmma::mma_sync(acc[i][j], fAh[i], fBh[j], acc[i][j]);
            {
                wmma::fragment<wmma::matrix_b, 16, 16, 16, __nv_bfloat16, wmma::row_major> fBl[2];
#pragma unroll
                for (int j = 0; j < 2; j++)
                    wmma::load_matrix_sync(fBl[j], bL + kk * BP + wn0 + j * 16, BP);
#pragma unroll
                for (int i = 0; i < 2; i++)
#pragma unroll
                    for (int j = 0; j < 2; j++)
                        wmma::mma_sync(acc[i][j], fAh[i], fBl[j], acc[i][j]);
            }
            {
                wmma::fragment<wmma::matrix_a, 16, 16, 16, __nv_bfloat16, wmma::col_major> fAl[2];
#pragma unroll
                for (int i = 0; i < 2; i++)
                    wmma::load_matrix_sync(fAl[i], aL + kk * AP + wm0 + i * 16, AP);
#pragma unroll
                for (int i = 0; i < 2; i++)
#pragma unroll
                    for (int j = 0; j < 2; j++)
                        wmma::mma_sync(acc[i][j], fAl[i], fBh[j], acc[i][j]);
            }
        }
#pragma unroll
        for (int i = 0; i < 2; i++)
#pragma unroll
            for (int j = 0; j < 2; j++)
                wmma::store_matrix_sync(Cs + (wm0 + i * 16) * CP + wn0 + j * 16,
                                        acc[i][j], CP, wmma::mem_row_major);
        __syncthreads();

        const int r = tid >> 2;
        const int c0 = (tid & 3) * 32;
        float tm = -1e30f;
#pragma unroll
        for (int c = 0; c < 32; c++) tm = fmaxf(tm, Cs[r * CP + c0 + c]);
        tm = fmaxf(tm, __shfl_xor_sync(0xffffffffu, tm, 1, 4));
        tm = fmaxf(tm, __shfl_xor_sync(0xffffffffu, tm, 2, 4));
        if ((tid & 3) == 0) atomicMax(&rm[r], enc_f(tm));
        __syncthreads();

        const float thr = dec_f(rm[r]) - 0.5f;
        const int m0 = mt * 128;
#pragma unroll
        for (int c = 0; c < 32; c++) {
            const float v = Cs[r * CP + c0 + c];
            if (v >= thr) {
                int pos = atomicAdd(&cnt[r], 1);
                if (pos < CAND) {
                    cm[r * CAND + pos]  = m0 + c0 + c;
                    csv[r * CAND + pos] = v;
                }
            }
        }
        __syncthreads();
    }

    if (tid < 64) {
        const float fmax = dec_f(rm[tid]);
        const float thrF = fmax - 0.5f;
        const int nc = cnt[tid] < CAND ? cnt[tid] : CAND;
        int hits = 0;
        for (int j = 0; j < nc; j++) {
            if (csv[tid * CAND + j] >= thrF) {
                cm[tid * CAND + hits] = cm[tid * CAND + j];
                hits++;
            }
        }
        cnt[tid] = hits;
        wrow[tid] = (fabsf(fmax) > 0.5f && hits > 0) ? 1.f / (float)hits : 0.f;
    }
    __syncthreads();

    const float* Yh = Y + (size_t)h * Dc * Nc;
    for (int rr = 0; rr < 8; rr++) {
        const int r = w * 8 + rr;
        const float wv = wrow[r];
        const int hits = cnt[r];
        if (wv == 0.f || hits == 0) continue;
        const int n = r0 + r;
        float yv[16];
#pragma unroll
        for (int p = 0; p < 16; p++)
            yv[p] = wv * Yh[(size_t)(lane + p * 32) * Nc + n];
        for (int j = 0; j < hits; j++) {
            const int m = cm[r * CAND + j];
#pragma unroll
            for (int p = 0; p < 16; p++)
                atomicAdd(&attn[(size_t)(lane + p * 32) * Nc + m], yv[p]);
        }
    }
}

// --------------------------------------------------------------------------
extern "C" void kernel_launch(void* const* d_in, const int* in_sizes, int n_in,
                              void* d_out, int out_size)
{
    const float* X  = (const float*)d_in[0];
    const float* Kp = (const float*)d_in[1];
    const float* Vp = (const float*)d_in[2];
    const float* W1 = (const float*)d_in[3];
    const float* b1 = (const float*)d_in[4];
    const float* W2 = (const float*)d_in[5];
    const float* b2 = (const float*)d_in[6];

    float *gX, *gAttn, *gY;
    __nv_bfloat16 *gKh, *gKl, *gVh, *gVl, *gW1h, *gW1l, *gW2h, *gW2l;
    __nv_bfloat16 *gXh, *gXl, *gAth, *gAtl, *gF1h, *gF1l, *gKXh, *gKXl;
    cudaGetSymbolAddress((void**)&gX,   g_X);
    cudaGetSymbolAddress((void**)&gAttn,g_attn);
    cudaGetSymbolAddress((void**)&gY,   g_Y);
    cudaGetSymbolAddress((void**)&gKh,  g_Kh);   cudaGetSymbolAddress((void**)&gKl,  g_Kl);
    cudaGetSymbolAddress((void**)&gVh,  g_Vh);   cudaGetSymbolAddress((void**)&gVl,  g_Vl);
    cudaGetSymbolAddress((void**)&gW1h, g_W1h);  cudaGetSymbolAddress((void**)&gW1l, g_W1l);
    cudaGetSymbolAddress((void**)&gW2h, g_W2h);  cudaGetSymbolAddress((void**)&gW2l, g_W2l);
    cudaGetSymbolAddress((void**)&gXh,  g_Xh);   cudaGetSymbolAddress((void**)&gXl,  g_Xl);
    cudaGetSymbolAddress((void**)&gAth, g_Ath);  cudaGetSymbolAddress((void**)&gAtl, g_Atl);
    cudaGetSymbolAddress((void**)&gF1h, g_F1h);  cudaGetSymbolAddress((void**)&gF1l, g_F1l);
    cudaGetSymbolAddress((void**)&gKXh, g_KXh);  cudaGetSymbolAddress((void**)&gKXl, g_KXl);

    const int SMY  = 4 * (2 * 128 * 40 * 2 + 2 * 32 * 264 * 2);   // 217088
    const int SMF2 = 4 * (2 *  64 * 40 * 2 + 2 * 32 * 136 * 2);   // 110592
    const int SMKX = 4 * (2 *  64 * 40 * 2 + 2 * 32 *  72 * 2);   // 77824
    const int SMGR = 171776;
    cudaFuncSetAttribute(bf16_gemm<128, 256, 2, 4, 4>,
                         cudaFuncAttributeMaxDynamicSharedMemorySize, SMY);
    cudaFuncSetAttribute(bf16_gemm<64, 128, 2, 2, 4>,
                         cudaFuncAttributeMaxDynamicSharedMemorySize, SMF2);
    cudaFuncSetAttribute(bf16_gemm<64, 64, 2, 2, 4>,
                         cudaFuncAttributeMaxDynamicSharedMemorySize, SMKX);
    cudaFuncSetAttribute(gram_argmax_scatter,
                         cudaFuncAttributeMaxDynamicSharedMemorySize, SMGR);

    {
        const int nK  = Lc * Hc * Qc * Dc / 4;
        const int nV  = Lc * Hc * Dc * Dc / 4;
        const int nW  = Lc * DFFc * Dc / 4;
        const int nX  = Dc * Nc / 4;
        split_kernel<<<(nK + 255) / 256, 256>>>((const float4*)Kp, gKh, gKl, nK);
        split_kernel<<<(nV + 255) / 256, 256>>>((const float4*)Vp, gVh, gVl, nV);
        split_kernel<<<(nW + 255) / 256, 256>>>((const float4*)W1, gW1h, gW1l, nW);
        split_kernel<<<(nW + 255) / 256, 256>>>((const float4*)W2, gW2h, gW2l, nW);
        split_kernel<<<(nX + 255) / 256, 256>>>((const float4*)X,  gXh,  gXl,  nX);
    }
    cudaMemcpyAsync(gX, X, (size_t)Dc * Nc * sizeof(float),
                    cudaMemcpyDeviceToDevice);

    for (int l = 0; l < Lc; l++) {
        const float* b1l = b1 + (size_t)l * DFFc;
        const float* b2l = b2 + (size_t)l * Dc;

        // 1) KX planes = K_l @ X  (mode 8: both planes)
        bf16_gemm<64, 64, 2, 2, 4><<<dim3(Nc / 64, (Hc * Qc) / 64, 1), 128, SMKX>>>(
            gKh + (size_t)l * Hc * Qc * Dc, gKl + (size_t)l * Hc * Qc * Dc,
            gXh, gXl, nullptr, gKXh, gKXl,
            Hc * Qc, Nc, Dc, 0, 0, nullptr, nullptr, 8);

        // 2) Y[h] = V_lh @ X  (mode 4, 128 blocks)
        bf16_gemm<128, 256, 2, 4, 4><<<dim3(Nc / 256, Dc / 128, Hc), 256, SMY>>>(
            gVh + (size_t)l * Hc * Dc * Dc, gVl + (size_t)l * Hc * Dc * Dc,
            gXh, gXl, gY, nullptr, nullptr,
            Dc, Nc, Dc, (long long)Dc * Dc, (long long)Dc * Nc,
            nullptr, nullptr, 4);

        // 3) attn = X
        cudaMemcpyAsync(gAttn, gX, (size_t)Dc * Nc * sizeof(float),
                        cudaMemcpyDeviceToDevice);

        // 4) fused gram+argmax+scatter (3-product, h+l)
        gram_argmax_scatter<<<dim3(Nc / 64, Hc), 256, SMGR>>>(gKXh, gKXl, gY, gAttn);

        // 5) attn planes
        split_kernel<<<(Dc * Nc / 4 + 255) / 256, 256>>>(
            (const float4*)gAttn, gAth, gAtl, Dc * Nc / 4);

        // 6) ff1 planes = relu(W1_l @ attn + b1)  (mode 9, 128 blocks)
        bf16_gemm<128, 256, 2, 4, 4><<<dim3(Nc / 256, DFFc / 128, 1), 256, SMY>>>(
            gW1h + (size_t)l * DFFc * Dc, gW1l + (size_t)l * DFFc * Dc,
            gAth, gAtl, nullptr, gF1h, gF1l,
            DFFc, Nc, Dc, 0, 0, b1l, nullptr, 9);

        // 7) X = attn + W2_l @ ff1 + b2  (mode 14)
        bf16_gemm<64, 128, 2, 2, 4><<<dim3(Nc / 128, Dc / 64, 1), 128, SMF2>>>(
            gW2h + (size_t)l * Dc * DFFc, gW2l + (size_t)l * Dc * DFFc,
            gF1h, gF1l, gX, gXh, gXl,
            Dc, Nc, DFFc, 0, 0, b2l, gAttn, 14);
    }

    cudaMemcpyAsync(d_out, gX, (size_t)Dc * Nc * sizeof(float),
                    cudaMemcpyDeviceToDevice);
}